// round 2
// baseline (speedup 1.0000x reference)
#include <cuda_runtime.h>

// scaled_dot_attention: B=32, S=2048, D=64, fp32
// scores = QK^T / 8;  masked -> -inf;  dropout(p=0.2) BEFORE softmax with
// JAX threefry (key 42, partitionable mode);  out = softmax(scores) @ V.

#define S_LEN  2048
#define D_HEAD 64
#define QTILE  128
#define KTILE  32
#define NTHR   256

static __device__ __forceinline__ float ex2f(float x) {
    float y;
    asm("ex2.approx.ftz.f32 %0, %1;" : "=f"(y) : "f"(x));
    return y;
}

// threefry2x32 with key (k0=0, k1=42), counter (0, n); returns out0 ^ out1
// (JAX partitionable random_bits for 32-bit draws, size < 2^32).
static __device__ __forceinline__ unsigned int threefry_bits(unsigned int n) {
    unsigned int x0 = 0u;        // c0 + ks0, ks0 = 0
    unsigned int x1 = n + 42u;   // c1 + ks1, ks1 = 42
#define TF_R(r) { x0 += x1; x1 = __funnelshift_l(x1, x1, (r)); x1 ^= x0; }
    TF_R(13) TF_R(15) TF_R(26) TF_R(6)
    x0 += 42u;          x1 += 0x1BD11BF0u + 1u;   // ks2 = 0x1BD11BDA ^ 0 ^ 42
    TF_R(17) TF_R(29) TF_R(16) TF_R(24)
    x0 += 0x1BD11BF0u;  x1 += 0u + 2u;
    TF_R(13) TF_R(15) TF_R(26) TF_R(6)
    x0 += 0u;           x1 += 42u + 3u;
    TF_R(17) TF_R(29) TF_R(16) TF_R(24)
    x0 += 42u;          x1 += 0x1BD11BF0u + 4u;
    TF_R(13) TF_R(15) TF_R(26) TF_R(6)
    x0 += 0x1BD11BF0u;  x1 += 0u + 5u;
#undef TF_R
    return x0 ^ x1;
}

// t = s' * log2(e), where s' = (dot/8)/0.8 for kept entries.
// 0.15625 * log2(e):
#define T_SCALE 0.22542110013890053f
// keep  <=>  (bits >> 9) < 6710887  <=>  bits < 0xCCCCCE00
#define KEEP_THRESH 0xCCCCCE00u

__global__ void __launch_bounds__(NTHR, 2)
attn_kernel(const float* __restrict__ Kg_, const float* __restrict__ Vg_,
            const float* __restrict__ Qg_, const unsigned char* __restrict__ maskg,
            float* __restrict__ outg)
{
    extern __shared__ float smem[];
    float* Qs  = smem;                     // [64][128] transposed  (8192 f)
    float* Ks  = Qs + 64 * QTILE;          // [64][32]  transposed  (2048 f)
    float* Vs  = Ks + 64 * KTILE;          // [32][64]  natural     (2048 f)
    float* Ps  = Vs + KTILE * D_HEAD;      // [128][36] padded      (4608 f)
    float* m_s = Ps + QTILE * 36;          // [128]
    float* l_s = m_s + QTILE;              // [128]
    float* sc_s = l_s + QTILE;             // [128]

    const int qt  = blockIdx.x;
    const int b   = blockIdx.y;
    const int q0  = qt * QTILE;
    const int tid = threadIdx.x;
    const int qg  = tid >> 3;        // 0..31 : q-group (4 rows)
    const int kg  = tid & 7;         // 0..7  : k-group (4 cols) / d-group (8 cols)
    const int qb  = qg * 4;
    const int db  = kg * 8;

    // ---- load Q tile transposed: Qs[d][r] ----
    const float* Qg = Qg_ + ((size_t)b * S_LEN + q0) * D_HEAD;
    #pragma unroll
    for (int i = 0; i < 8; i++) {
        int e = tid + i * NTHR;                 // float4 index into 128x64
        float4 v = ((const float4*)Qg)[e];
        int r = (e * 4) / D_HEAD;
        int d = (e * 4) % D_HEAD;
        Qs[(d + 0) * QTILE + r] = v.x;
        Qs[(d + 1) * QTILE + r] = v.y;
        Qs[(d + 2) * QTILE + r] = v.z;
        Qs[(d + 3) * QTILE + r] = v.w;
    }
    if (tid < QTILE) { m_s[tid] = -1e30f; l_s[tid] = 0.0f; }

    float O[4][8];
    #pragma unroll
    for (int i = 0; i < 4; i++)
        #pragma unroll
        for (int j = 0; j < 8; j++) O[i][j] = 0.0f;

    // flat rng index base for this thread's first q row: (b*S + q)*S
    const unsigned int nbase0 = (unsigned int)(b * S_LEN + q0 + qb) * (unsigned int)S_LEN;
    const unsigned char* mrow = maskg + (size_t)b * S_LEN * S_LEN + (size_t)(q0 + qb) * S_LEN;

    for (int k0 = 0; k0 < S_LEN; k0 += KTILE) {
        __syncthreads();   // previous AV reads done before K/V/P overwrite

        // ---- load K (transposed) and V (natural) tiles ----
        const float* Kg = Kg_ + ((size_t)b * S_LEN + k0) * D_HEAD;
        const float* Vg = Vg_ + ((size_t)b * S_LEN + k0) * D_HEAD;
        #pragma unroll
        for (int i = 0; i < 2; i++) {
            int e = tid + i * NTHR;             // float4 idx into 32x64 (512 total)
            float4 kv4 = ((const float4*)Kg)[e];
            int r = (e * 4) / D_HEAD;
            int d = (e * 4) % D_HEAD;
            Ks[(d + 0) * KTILE + r] = kv4.x;
            Ks[(d + 1) * KTILE + r] = kv4.y;
            Ks[(d + 2) * KTILE + r] = kv4.z;
            Ks[(d + 3) * KTILE + r] = kv4.w;
            ((float4*)Vs)[e] = ((const float4*)Vg)[e];
        }
        __syncthreads();

        // ---- scores: 4q x 4k per thread ----
        float acc[4][4];
        #pragma unroll
        for (int i = 0; i < 4; i++)
            #pragma unroll
            for (int j = 0; j < 4; j++) acc[i][j] = 0.0f;

        const float4* Qs4 = (const float4*)Qs;
        const float4* Ks4 = (const float4*)Ks;
        #pragma unroll 8
        for (int d = 0; d < D_HEAD; d++) {
            float4 qv = Qs4[d * (QTILE / 4) + qg];
            float4 kv = Ks4[d * (KTILE / 4) + kg];
            acc[0][0] += qv.x * kv.x; acc[0][1] += qv.x * kv.y; acc[0][2] += qv.x * kv.z; acc[0][3] += qv.x * kv.w;
            acc[1][0] += qv.y * kv.x; acc[1][1] += qv.y * kv.y; acc[1][2] += qv.y * kv.z; acc[1][3] += qv.y * kv.w;
            acc[2][0] += qv.z * kv.x; acc[2][1] += qv.z * kv.y; acc[2][2] += qv.z * kv.z; acc[2][3] += qv.z * kv.w;
            acc[3][0] += qv.w * kv.x; acc[3][1] += qv.w * kv.y; acc[3][2] += qv.w * kv.z; acc[3][3] += qv.w * kv.w;
        }

        // ---- threefry keep mask for the 16 elements (looped: small code size) ----
        unsigned int keepmask = 0u;
        const unsigned int kcol = (unsigned int)(k0 + kg * 4);
        #pragma unroll 1
        for (int e = 0; e < 16; ++e) {
            unsigned int n = nbase0 + (unsigned int)(e >> 2) * S_LEN + kcol + (unsigned int)(e & 3);
            if (threefry_bits(n) < KEEP_THRESH) keepmask |= (1u << e);
        }

        // ---- mask + dropout + scale to log2 domain ----
        #pragma unroll
        for (int i = 0; i < 4; i++) {
            unsigned int mb = *(const unsigned int*)(mrow + (size_t)i * S_LEN + k0 + kg * 4);
            #pragma unroll
            for (int j = 0; j < 4; j++) {
                bool masked = ((mb >> (8 * j)) & 0xffu) != 0u;
                bool keep   = (keepmask >> (i * 4 + j)) & 1u;
                float t = acc[i][j] * T_SCALE;
                if (masked) t = -1e30f;
                acc[i][j] = keep ? t : 0.0f;
            }
        }

        // ---- online softmax (row stats across 8 lanes of the q-row group) ----
        #pragma unroll
        for (int i = 0; i < 4; i++) {
            int q = qb + i;
            float tmax = fmaxf(fmaxf(acc[i][0], acc[i][1]), fmaxf(acc[i][2], acc[i][3]));
            tmax = fmaxf(tmax, __shfl_xor_sync(0xffffffffu, tmax, 1));
            tmax = fmaxf(tmax, __shfl_xor_sync(0xffffffffu, tmax, 2));
            tmax = fmaxf(tmax, __shfl_xor_sync(0xffffffffu, tmax, 4));
            float m_old = m_s[q];
            float m_new = fmaxf(m_old, tmax);
            float psum = 0.0f;
            #pragma unroll
            for (int j = 0; j < 4; j++) {
                float p = ex2f(acc[i][j] - m_new);
                acc[i][j] = p;
                psum += p;
            }
            psum += __shfl_xor_sync(0xffffffffu, psum, 1);
            psum += __shfl_xor_sync(0xffffffffu, psum, 2);
            psum += __shfl_xor_sync(0xffffffffu, psum, 4);
            if (kg == 0) {
                float sc = ex2f(m_old - m_new);
                l_s[q] = l_s[q] * sc + psum;
                m_s[q] = m_new;
                sc_s[q] = sc;
            }
            *(float4*)(Ps + q * 36 + kg * 4) =
                make_float4(acc[i][0], acc[i][1], acc[i][2], acc[i][3]);
        }
        __syncwarp();   // P / stats are produced & consumed within one warp

        // ---- AV: O[4q][8d] += P[4q][32k] * V[32k][8d] ----
        float scl[4];
        #pragma unroll
        for (int i = 0; i < 4; i++) scl[i] = sc_s[qb + i];
        #pragma unroll
        for (int i = 0; i < 4; i++)
            #pragma unroll
            for (int j = 0; j < 8; j++) O[i][j] *= scl[i];

        const float4* Vs4 = (const float4*)Vs;
        #pragma unroll
        for (int k4 = 0; k4 < KTILE; k4 += 4) {
            float4 p[4];
            #pragma unroll
            for (int i = 0; i < 4; i++)
                p[i] = *(const float4*)(Ps + (qb + i) * 36 + k4);
            #pragma unroll
            for (int kk = 0; kk < 4; kk++) {
                float4 v0 = Vs4[(k4 + kk) * (D_HEAD / 4) + kg * 2];
                float4 v1 = Vs4[(k4 + kk) * (D_HEAD / 4) + kg * 2 + 1];
                #pragma unroll
                for (int i = 0; i < 4; i++) {
                    float pv = (kk == 0) ? p[i].x : (kk == 1) ? p[i].y : (kk == 2) ? p[i].z : p[i].w;
                    O[i][0] += pv * v0.x; O[i][1] += pv * v0.y;
                    O[i][2] += pv * v0.z; O[i][3] += pv * v0.w;
                    O[i][4] += pv * v1.x; O[i][5] += pv * v1.y;
                    O[i][6] += pv * v1.z; O[i][7] += pv * v1.w;
                }
            }
        }
    }

    // ---- epilogue: divide by l, store ----
    #pragma unroll
    for (int i = 0; i < 4; i++) {
        int q = qb + i;
        float inv = 1.0f / l_s[q];
        float* og = outg + ((size_t)b * S_LEN + (q0 + q)) * D_HEAD + db;
        *(float4*)(og)     = make_float4(O[i][0] * inv, O[i][1] * inv, O[i][2] * inv, O[i][3] * inv);
        *(float4*)(og + 4) = make_float4(O[i][4] * inv, O[i][5] * inv, O[i][6] * inv, O[i][7] * inv);
    }
}

extern "C" void kernel_launch(void* const* d_in, const int* in_sizes, int n_in,
                              void* d_out, int out_size) {
    const float*         K    = (const float*)d_in[0];
    const float*         V    = (const float*)d_in[1];
    const float*         Q    = (const float*)d_in[2];
    const unsigned char* mask = (const unsigned char*)d_in[3];
    float*               out  = (float*)d_out;

    const int B = in_sizes[2] / (S_LEN * D_HEAD);   // 32
    const int smem_bytes = (64 * QTILE + 64 * KTILE + KTILE * D_HEAD +
                            QTILE * 36 + 3 * QTILE) * (int)sizeof(float);  // 69120

    cudaFuncSetAttribute(attn_kernel,
                         cudaFuncAttributeMaxDynamicSharedMemorySize, smem_bytes);

    dim3 grid(S_LEN / QTILE, B);
    attn_kernel<<<grid, NTHR, smem_bytes>>>(K, V, Q, mask, out);
}

// round 3
// speedup vs baseline: 1.0018x; 1.0018x over previous
#include <cuda_runtime.h>

// scaled_dot_attention: B=32, S=2048, D=64, fp32
// scores = QK^T / 8;  masked -> -inf;  dropout(p=0.2) BEFORE softmax with
// JAX threefry (key 42, partitionable mode);  out = softmax(scores) @ V.

#define S_LEN  2048
#define D_HEAD 64
#define QTILE  128
#define KTILE  32
#define NTHR   256

static __device__ __forceinline__ float ex2f(float x) {
    float y;
    asm("ex2.approx.ftz.f32 %0, %1;" : "=f"(y) : "f"(x));
    return y;
}

// threefry2x32 with key (k0=0, k1=42), counter (0, n); returns out0 ^ out1
// (JAX partitionable random_bits for 32-bit draws, size < 2^32).
static __device__ __forceinline__ unsigned int threefry_bits(unsigned int n) {
    unsigned int x0 = 0u;        // c0 + ks0, ks0 = 0
    unsigned int x1 = n + 42u;   // c1 + ks1, ks1 = 42
#define TF_R(r) { x0 += x1; x1 = __funnelshift_l(x1, x1, (r)); x1 ^= x0; }
    TF_R(13) TF_R(15) TF_R(26) TF_R(6)
    x0 += 42u;          x1 += 0x1BD11BF0u + 1u;   // ks2 = 0x1BD11BDA ^ 0 ^ 42
    TF_R(17) TF_R(29) TF_R(16) TF_R(24)
    x0 += 0x1BD11BF0u;  x1 += 0u + 2u;
    TF_R(13) TF_R(15) TF_R(26) TF_R(6)
    x0 += 0u;           x1 += 42u + 3u;
    TF_R(17) TF_R(29) TF_R(16) TF_R(24)
    x0 += 42u;          x1 += 0x1BD11BF0u + 4u;
    TF_R(13) TF_R(15) TF_R(26) TF_R(6)
    x0 += 0x1BD11BF0u;  x1 += 0u + 5u;
#undef TF_R
    return x0 ^ x1;
}

// t = s' * log2(e), where s' = (dot/8)/0.8 for kept entries.
// 0.15625 * log2(e):
#define T_SCALE 0.22542110013890053f
// keep  <=>  (bits >> 9) < 6710887  <=>  bits < 0xCCCCCE00
#define KEEP_THRESH 0xCCCCCE00u

__global__ void __launch_bounds__(NTHR, 2)
attn_kernel(const float* __restrict__ Kg_, const float* __restrict__ Vg_,
            const float* __restrict__ Qg_, const unsigned char* __restrict__ maskg,
            float* __restrict__ outg)
{
    extern __shared__ float smem[];
    float* Qs  = smem;                     // [64][128] transposed  (8192 f)
    float* Ks  = Qs + 64 * QTILE;          // [64][32]  transposed  (2048 f)
    float* Vs  = Ks + 64 * KTILE;          // [32][64]  natural     (2048 f)
    float* Ps  = Vs + KTILE * D_HEAD;      // [128][36] padded      (4608 f)
    float* m_s = Ps + QTILE * 36;          // [128]
    float* l_s = m_s + QTILE;              // [128]
    float* sc_s = l_s + QTILE;             // [128]

    const int qt  = blockIdx.x;
    const int b   = blockIdx.y;
    const int q0  = qt * QTILE;
    const int tid = threadIdx.x;
    const int qg  = tid >> 3;        // 0..31 : q-group (4 rows)
    const int kg  = tid & 7;         // 0..7  : k-group (4 cols) / d-group (8 cols)
    const int qb  = qg * 4;
    const int db  = kg * 8;

    // ---- load Q tile transposed: Qs[d][r] ----
    const float* Qg = Qg_ + ((size_t)b * S_LEN + q0) * D_HEAD;
    #pragma unroll
    for (int i = 0; i < 8; i++) {
        int e = tid + i * NTHR;                 // float4 index into 128x64
        float4 v = ((const float4*)Qg)[e];
        int r = (e * 4) / D_HEAD;
        int d = (e * 4) % D_HEAD;
        Qs[(d + 0) * QTILE + r] = v.x;
        Qs[(d + 1) * QTILE + r] = v.y;
        Qs[(d + 2) * QTILE + r] = v.z;
        Qs[(d + 3) * QTILE + r] = v.w;
    }
    if (tid < QTILE) { m_s[tid] = -1e30f; l_s[tid] = 0.0f; }

    float O[4][8];
    #pragma unroll
    for (int i = 0; i < 4; i++)
        #pragma unroll
        for (int j = 0; j < 8; j++) O[i][j] = 0.0f;

    // flat rng index base for this thread's first q row: (b*S + q)*S
    const unsigned int nbase0 = (unsigned int)(b * S_LEN + q0 + qb) * (unsigned int)S_LEN;
    const unsigned char* mrow = maskg + (size_t)b * S_LEN * S_LEN + (size_t)(q0 + qb) * S_LEN;

    for (int k0 = 0; k0 < S_LEN; k0 += KTILE) {
        __syncthreads();   // previous AV reads done before K/V/P overwrite

        // ---- load K (transposed) and V (natural) tiles ----
        const float* Kg = Kg_ + ((size_t)b * S_LEN + k0) * D_HEAD;
        const float* Vg = Vg_ + ((size_t)b * S_LEN + k0) * D_HEAD;
        #pragma unroll
        for (int i = 0; i < 2; i++) {
            int e = tid + i * NTHR;             // float4 idx into 32x64 (512 total)
            float4 kv4 = ((const float4*)Kg)[e];
            int r = (e * 4) / D_HEAD;
            int d = (e * 4) % D_HEAD;
            Ks[(d + 0) * KTILE + r] = kv4.x;
            Ks[(d + 1) * KTILE + r] = kv4.y;
            Ks[(d + 2) * KTILE + r] = kv4.z;
            Ks[(d + 3) * KTILE + r] = kv4.w;
            ((float4*)Vs)[e] = ((const float4*)Vg)[e];
        }
        __syncthreads();

        // ---- scores: 4q x 4k per thread ----
        float acc[4][4];
        #pragma unroll
        for (int i = 0; i < 4; i++)
            #pragma unroll
            for (int j = 0; j < 4; j++) acc[i][j] = 0.0f;

        const float4* Qs4 = (const float4*)Qs;
        const float4* Ks4 = (const float4*)Ks;
        #pragma unroll 8
        for (int d = 0; d < D_HEAD; d++) {
            float4 qv = Qs4[d * (QTILE / 4) + qg];
            float4 kv = Ks4[d * (KTILE / 4) + kg];
            acc[0][0] += qv.x * kv.x; acc[0][1] += qv.x * kv.y; acc[0][2] += qv.x * kv.z; acc[0][3] += qv.x * kv.w;
            acc[1][0] += qv.y * kv.x; acc[1][1] += qv.y * kv.y; acc[1][2] += qv.y * kv.z; acc[1][3] += qv.y * kv.w;
            acc[2][0] += qv.z * kv.x; acc[2][1] += qv.z * kv.y; acc[2][2] += qv.z * kv.z; acc[2][3] += qv.z * kv.w;
            acc[3][0] += qv.w * kv.x; acc[3][1] += qv.w * kv.y; acc[3][2] += qv.w * kv.z; acc[3][3] += qv.w * kv.w;
        }

        // ---- threefry keep mask for the 16 elements (looped: small code size) ----
        unsigned int keepmask = 0u;
        const unsigned int kcol = (unsigned int)(k0 + kg * 4);
        #pragma unroll 1
        for (int e = 0; e < 16; ++e) {
            unsigned int n = nbase0 + (unsigned int)(e >> 2) * S_LEN + kcol + (unsigned int)(e & 3);
            if (threefry_bits(n) < KEEP_THRESH) keepmask |= (1u << e);
        }

        // ---- mask + dropout + scale to log2 domain ----
        #pragma unroll
        for (int i = 0; i < 4; i++) {
            unsigned int mb = *(const unsigned int*)(mrow + (size_t)i * S_LEN + k0 + kg * 4);
            #pragma unroll
            for (int j = 0; j < 4; j++) {
                bool masked = ((mb >> (8 * j)) & 0xffu) != 0u;
                bool keep   = (keepmask >> (i * 4 + j)) & 1u;
                float t = acc[i][j] * T_SCALE;
                if (masked) t = -1e30f;
                acc[i][j] = keep ? t : 0.0f;
            }
        }

        // ---- online softmax (row stats across 8 lanes of the q-row group) ----
        #pragma unroll
        for (int i = 0; i < 4; i++) {
            int q = qb + i;
            float tmax = fmaxf(fmaxf(acc[i][0], acc[i][1]), fmaxf(acc[i][2], acc[i][3]));
            tmax = fmaxf(tmax, __shfl_xor_sync(0xffffffffu, tmax, 1));
            tmax = fmaxf(tmax, __shfl_xor_sync(0xffffffffu, tmax, 2));
            tmax = fmaxf(tmax, __shfl_xor_sync(0xffffffffu, tmax, 4));
            float m_old = m_s[q];
            float m_new = fmaxf(m_old, tmax);
            float psum = 0.0f;
            #pragma unroll
            for (int j = 0; j < 4; j++) {
                float p = ex2f(acc[i][j] - m_new);
                acc[i][j] = p;
                psum += p;
            }
            psum += __shfl_xor_sync(0xffffffffu, psum, 1);
            psum += __shfl_xor_sync(0xffffffffu, psum, 2);
            psum += __shfl_xor_sync(0xffffffffu, psum, 4);
            if (kg == 0) {
                float sc = ex2f(m_old - m_new);
                l_s[q] = l_s[q] * sc + psum;
                m_s[q] = m_new;
                sc_s[q] = sc;
            }
            *(float4*)(Ps + q * 36 + kg * 4) =
                make_float4(acc[i][0], acc[i][1], acc[i][2], acc[i][3]);
        }
        __syncwarp();   // P / stats are produced & consumed within one warp

        // ---- AV: O[4q][8d] += P[4q][32k] * V[32k][8d] ----
        float scl[4];
        #pragma unroll
        for (int i = 0; i < 4; i++) scl[i] = sc_s[qb + i];
        #pragma unroll
        for (int i = 0; i < 4; i++)
            #pragma unroll
            for (int j = 0; j < 8; j++) O[i][j] *= scl[i];

        const float4* Vs4 = (const float4*)Vs;
        #pragma unroll
        for (int k4 = 0; k4 < KTILE; k4 += 4) {
            float4 p[4];
            #pragma unroll
            for (int i = 0; i < 4; i++)
                p[i] = *(const float4*)(Ps + (qb + i) * 36 + k4);
            #pragma unroll
            for (int kk = 0; kk < 4; kk++) {
                float4 v0 = Vs4[(k4 + kk) * (D_HEAD / 4) + kg * 2];
                float4 v1 = Vs4[(k4 + kk) * (D_HEAD / 4) + kg * 2 + 1];
                #pragma unroll
                for (int i = 0; i < 4; i++) {
                    float pv = (kk == 0) ? p[i].x : (kk == 1) ? p[i].y : (kk == 2) ? p[i].z : p[i].w;
                    O[i][0] += pv * v0.x; O[i][1] += pv * v0.y;
                    O[i][2] += pv * v0.z; O[i][3] += pv * v0.w;
                    O[i][4] += pv * v1.x; O[i][5] += pv * v1.y;
                    O[i][6] += pv * v1.z; O[i][7] += pv * v1.w;
                }
            }
        }
    }

    // ---- epilogue: divide by l, store ----
    #pragma unroll
    for (int i = 0; i < 4; i++) {
        int q = qb + i;
        float inv = 1.0f / l_s[q];
        float* og = outg + ((size_t)b * S_LEN + (q0 + q)) * D_HEAD + db;
        *(float4*)(og)     = make_float4(O[i][0] * inv, O[i][1] * inv, O[i][2] * inv, O[i][3] * inv);
        *(float4*)(og + 4) = make_float4(O[i][4] * inv, O[i][5] * inv, O[i][6] * inv, O[i][7] * inv);
    }
}

extern "C" void kernel_launch(void* const* d_in, const int* in_sizes, int n_in,
                              void* d_out, int out_size) {
    const float*         K    = (const float*)d_in[0];
    const float*         V    = (const float*)d_in[1];
    const float*         Q    = (const float*)d_in[2];
    const unsigned char* mask = (const unsigned char*)d_in[3];
    float*               out  = (float*)d_out;

    const int B = in_sizes[2] / (S_LEN * D_HEAD);   // 32
    const int smem_bytes = (64 * QTILE + 64 * KTILE + KTILE * D_HEAD +
                            QTILE * 36 + 3 * QTILE) * (int)sizeof(float);  // 69120

    cudaFuncSetAttribute(attn_kernel,
                         cudaFuncAttributeMaxDynamicSharedMemorySize, smem_bytes);

    dim3 grid(S_LEN / QTILE, B);
    attn_kernel<<<grid, NTHR, smem_bytes>>>(K, V, Q, mask, out);
}

// round 5
// speedup vs baseline: 2.5898x; 2.5852x over previous
#include <cuda_runtime.h>
typedef unsigned int u32; typedef unsigned short u16;

#define SQ   2048
#define QT   64
#define KTL  64
#define NT   (SQ/KTL)
#define NTHR 128
#define STRB 144              // smem row stride bytes (72 bf16: 64 + 8 pad)

#define KHI 0
#define KLO (64*STRB)
#define VHI (2*64*STRB)
#define VLO (3*64*STRB)
#define SMEM_SZ (4*64*STRB)   // 36864 B

#define T_SCALE 0.22542110013890053f   // (1/(8*0.8))*log2(e)
#define M_LOG2  17.312340490667560f    // 12*log2(e) fixed softmax max
#define KEEP_T  0xCCCCCE00u

static __device__ __forceinline__ u32 smem_u32(const void* p){
    u32 a; asm("{ .reg .u64 t; cvta.to.shared.u64 t, %1; cvt.u32.u64 %0, t; }":"=r"(a):"l"(p)); return a;
}
static __device__ __forceinline__ float ex2f(float x){ float y; asm("ex2.approx.ftz.f32 %0,%1;":"=f"(y):"f"(x)); return y; }
static __device__ __forceinline__ u32 pack_bf16(float lo, float hi){
    u32 d; asm("cvt.rn.bf16x2.f32 %0, %1, %2;" : "=r"(d) : "f"(hi), "f"(lo)); return d;
}
static __device__ __forceinline__ float lo_f(u32 p){ return __uint_as_float(p<<16); }
static __device__ __forceinline__ float hi_f(u32 p){ return __uint_as_float(p & 0xffff0000u); }

// threefry2x32, key (0,42), counter (0,n) -> out0^out1 (validated in R1)
static __device__ __forceinline__ u32 threefry_bits(u32 n){
    u32 x0 = 0u, x1 = n + 42u;
#define TF_R(r) { x0 += x1; x1 = __funnelshift_l(x1,x1,(r)); x1 ^= x0; }
    TF_R(13) TF_R(15) TF_R(26) TF_R(6)
    x0 += 42u;         x1 += 0x1BD11BF0u + 1u;
    TF_R(17) TF_R(29) TF_R(16) TF_R(24)
    x0 += 0x1BD11BF0u; x1 += 0u + 2u;
    TF_R(13) TF_R(15) TF_R(26) TF_R(6)
    x0 += 0u;          x1 += 42u + 3u;
    TF_R(17) TF_R(29) TF_R(16) TF_R(24)
    x0 += 42u;         x1 += 0x1BD11BF0u + 4u;
    TF_R(13) TF_R(15) TF_R(26) TF_R(6)
    x0 += 0x1BD11BF0u; x1 += 0u + 5u;
#undef TF_R
    return x0 ^ x1;
}

static __device__ __forceinline__ void ldm4(u32* r, u32 a){
    asm volatile("ldmatrix.sync.aligned.m8n8.x4.shared.b16 {%0,%1,%2,%3},[%4];"
        : "=r"(r[0]),"=r"(r[1]),"=r"(r[2]),"=r"(r[3]) : "r"(a));
}
static __device__ __forceinline__ void ldm4t(u32* r, u32 a){
    asm volatile("ldmatrix.sync.aligned.m8n8.x4.trans.shared.b16 {%0,%1,%2,%3},[%4];"
        : "=r"(r[0]),"=r"(r[1]),"=r"(r[2]),"=r"(r[3]) : "r"(a));
}
static __device__ __forceinline__ void mma(float* c, const u32* a, const u32* b){
    asm volatile("mma.sync.aligned.m16n8k16.row.col.f32.bf16.bf16.f32 "
        "{%0,%1,%2,%3},{%4,%5,%6,%7},{%8,%9},{%0,%1,%2,%3};"
        : "+f"(c[0]),"+f"(c[1]),"+f"(c[2]),"+f"(c[3])
        : "r"(a[0]),"r"(a[1]),"r"(a[2]),"r"(a[3]),"r"(b[0]),"r"(b[1]));
}
// store 4 consecutive-k f32 as bf16 hi/lo pairs (8B aligned)
static __device__ __forceinline__ void st_hilo(char* bh, char* bl, float4 v){
    u32 h01 = pack_bf16(v.x, v.y), h23 = pack_bf16(v.z, v.w);
    u32 l01 = pack_bf16(v.x - lo_f(h01), v.y - hi_f(h01));
    u32 l23 = pack_bf16(v.z - lo_f(h23), v.w - hi_f(h23));
    *(uint2*)bh = make_uint2(h01, h23);
    *(uint2*)bl = make_uint2(l01, l23);
}
static __device__ __forceinline__ float epi(float c, u32 bits, u32 mb){
    float tt = fmaf(c, T_SCALE, -M_LOG2);
    if (mb) tt = -1e30f;            // masked -> -inf
    if (bits >= KEEP_T) tt = -M_LOG2;  // dropped -> score 0
    return ex2f(tt);
}

__global__ void __launch_bounds__(NTHR, 3)
attn_mma(const float* __restrict__ Kg, const float* __restrict__ Vg,
         const float* __restrict__ Qg, const unsigned char* __restrict__ Mg,
         float* __restrict__ Og)
{
    __shared__ __align__(128) char smem[SMEM_SZ];
    const int tid = threadIdx.x, w = tid>>5, lane = tid&31;
    const int b = blockIdx.y, q0 = blockIdx.x*QT;
    const int r0 = w*16 + (lane>>2);
    const int c2 = (lane&3)*2;
    const u32 sbase = smem_u32(smem);

    // ---- stage Q (64x64 f32) -> bf16 hi/lo in KHI/KLO area, then frags ----
    const float* Qp = Qg + ((size_t)(b*SQ + q0))*64;
    #pragma unroll
    for (int j=0;j<8;j++){
        int e = tid + j*NTHR;
        float4 v = ((const float4*)Qp)[e];
        int row = e>>4, k4 = (e&15)*4;
        st_hilo(smem + KHI + row*STRB + k4*2, smem + KLO + row*STRB + k4*2, v);
    }
    __syncthreads();
    u32 qh[4][4], ql[4][4];
    {
        u32 qa = sbase + (u32)((w*16 + ((lane>>3)&1)*8 + (lane&7))*STRB + ((lane>>4)&1)*16);
        #pragma unroll
        for (int s=0;s<4;s++){ ldm4(qh[s], qa + KHI + 32*s); ldm4(ql[s], qa + KLO + 32*s); }
    }

    float O[8][4];
    #pragma unroll
    for (int j=0;j<8;j++){ O[j][0]=0.f;O[j][1]=0.f;O[j][2]=0.f;O[j][3]=0.f; }
    float l0 = 0.f, l8 = 0.f;

    const u32 nb0 = (u32)((b*SQ + q0 + r0)*SQ);
    const unsigned char* m0 = Mg + ((size_t)(b*SQ + q0 + r0))*SQ;
    const u32 kb = sbase + (u32)(((((lane>>4)&1)*8) + (lane&7))*STRB + ((lane>>3)&1)*16);
    const u32 vb = sbase + (u32)(((((lane>>3)&1)*8) + (lane&7))*STRB + ((lane>>4)&1)*16);

    for (int t=0;t<NT;t++){
        const int k0 = t*KTL;
        __syncthreads();
        // ---- load K,V tile -> bf16 hi/lo smem ----
        const float* Kp = Kg + ((size_t)(b*SQ + k0))*64;
        const float* Vp = Vg + ((size_t)(b*SQ + k0))*64;
        #pragma unroll
        for (int j=0;j<8;j++){
            int e = tid + j*NTHR;
            int row = e>>4, k4 = (e&15)*4;
            float4 kv = ((const float4*)Kp)[e];
            st_hilo(smem + KHI + row*STRB + k4*2, smem + KLO + row*STRB + k4*2, kv);
            float4 vv = ((const float4*)Vp)[e];
            st_hilo(smem + VHI + row*STRB + k4*2, smem + VLO + row*STRB + k4*2, vv);
        }
        __syncthreads();

        // ---- QK^T: 3-term bf16 (QhKh + QlKh + QhKl) ----
        float C[8][4];
        #pragma unroll
        for (int j=0;j<8;j++){ C[j][0]=0.f;C[j][1]=0.f;C[j][2]=0.f;C[j][3]=0.f; }
        #pragma unroll
        for (int s=0;s<4;s++){
            #pragma unroll
            for (int jp=0;jp<4;jp++){
                u32 bh[4], bl[4];
                ldm4(bh, kb + KHI + (u32)(jp*16*STRB + 32*s));
                ldm4(bl, kb + KLO + (u32)(jp*16*STRB + 32*s));
                mma(C[2*jp],   qh[s], bh+0);  mma(C[2*jp+1], qh[s], bh+2);
                mma(C[2*jp],   ql[s], bh+0);  mma(C[2*jp+1], ql[s], bh+2);
                mma(C[2*jp],   qh[s], bl+0);  mma(C[2*jp+1], qh[s], bl+2);
            }
        }

        // ---- epilogue: threefry dropout + mask + exp2; pack P hi/lo A-frags ----
        u32 Ph[4][4], Pl[4][4];
        #pragma unroll
        for (int j=0;j<8;j++){
            u32 n00 = nb0 + (u32)(k0 + 8*j + c2);
            u32 b00 = threefry_bits(n00);
            u32 b01 = threefry_bits(n00 + 1u);
            u32 b10 = threefry_bits(n00 + 8u*SQ);
            u32 b11 = threefry_bits(n00 + 8u*SQ + 1u);
            u16 mw0 = *(const u16*)(m0 + k0 + 8*j + c2);
            u16 mw8 = *(const u16*)(m0 + 8*SQ + k0 + 8*j + c2);
            float p0 = epi(C[j][0], b00, mw0 & 0xffu);
            float p1 = epi(C[j][1], b01, mw0 >> 8);
            float p2 = epi(C[j][2], b10, mw8 & 0xffu);
            float p3 = epi(C[j][3], b11, mw8 >> 8);
            l0 += p0 + p1;  l8 += p2 + p3;
            u32 h01 = pack_bf16(p0, p1), h23 = pack_bf16(p2, p3);
            u32 lo01 = pack_bf16(p0 - lo_f(h01), p1 - hi_f(h01));
            u32 lo23 = pack_bf16(p2 - lo_f(h23), p3 - hi_f(h23));
            int s = j>>1, o = (j&1)*2;
            Ph[s][o] = h01; Ph[s][o+1] = h23;
            Pl[s][o] = lo01; Pl[s][o+1] = lo23;
        }

        // ---- AV: 3-term bf16 (PhVh + PlVh + PhVl), O accumulates ----
        #pragma unroll
        for (int s=0;s<4;s++){
            #pragma unroll
            for (int jp=0;jp<4;jp++){
                u32 bh[4], bl[4];
                ldm4t(bh, vb + VHI + (u32)(s*16*STRB + jp*32));
                ldm4t(bl, vb + VLO + (u32)(s*16*STRB + jp*32));
                mma(O[2*jp],   Ph[s], bh+0);  mma(O[2*jp+1], Ph[s], bh+2);
                mma(O[2*jp],   Pl[s], bh+0);  mma(O[2*jp+1], Pl[s], bh+2);
                mma(O[2*jp],   Ph[s], bl+0);  mma(O[2*jp+1], Ph[s], bl+2);
            }
        }
    }

    // ---- finalize: reduce l across quad lanes, normalize, store ----
    l0 += __shfl_xor_sync(0xffffffffu, l0, 1);
    l0 += __shfl_xor_sync(0xffffffffu, l0, 2);
    l8 += __shfl_xor_sync(0xffffffffu, l8, 1);
    l8 += __shfl_xor_sync(0xffffffffu, l8, 2);
    float i0 = 1.0f / l0, i8 = 1.0f / l8;
    float* o0 = Og + ((size_t)(b*SQ + q0 + r0))*64;
    #pragma unroll
    for (int j=0;j<8;j++){
        *(float2*)(o0 + 8*j + c2)       = make_float2(O[j][0]*i0, O[j][1]*i0);
        *(float2*)(o0 + 512 + 8*j + c2) = make_float2(O[j][2]*i8, O[j][3]*i8);
    }
}

extern "C" void kernel_launch(void* const* d_in, const int* in_sizes, int n_in,
                              void* d_out, int out_size) {
    const float* K = (const float*)d_in[0];
    const float* V = (const float*)d_in[1];
    const float* Q = (const float*)d_in[2];
    const unsigned char* mask = (const unsigned char*)d_in[3];
    float* out = (float*)d_out;
    dim3 grid(SQ/QT, 32);
    attn_mma<<<grid, NTHR>>>(K, V, Q, mask, out);
}